// round 16
// baseline (speedup 1.0000x reference)
#include <cuda_runtime.h>
#include <cuda_fp16.h>
#include <cstdint>

#define N_PTS 8192
#define DTOK  256
#define KNN_K 16
#define D_IN  259          // DTOK + 3
#define KPAD  272          // D_IN padded to multiple of 16 (rows 16B-aligned)
#define NW    512          // concatenated output cols of gemm1: [A | B]

typedef unsigned long long u64;

// ---------------- f32x2 packed helpers (sm_100+) ----------------------------
__device__ __forceinline__ u64 pack2(float lo, float hi) {
    u64 r;
    asm("mov.b64 %0, {%1, %2};" : "=l"(r) : "f"(lo), "f"(hi));
    return r;
}
__device__ __forceinline__ u64 fma2(u64 a, u64 b, u64 c) {
    u64 d;
    asm("fma.rn.f32x2 %0, %1, %2, %3;" : "=l"(d) : "l"(a), "l"(b), "l"(c));
    return d;
}
__device__ __forceinline__ float2 unpack2(u64 v) {
    float2 f;
    asm("mov.b64 {%0, %1}, %2;" : "=f"(f.x), "=f"(f.y) : "l"(v));
    return f;
}

// ---------------- warp MMA helpers (family-level PTX) ------------------------
__device__ __forceinline__ uint32_t smem_u32(const void* p) {
    uint32_t a;
    asm("{ .reg .u64 t; cvta.to.shared.u64 t, %1; cvt.u32.u64 %0, t; }" : "=r"(a) : "l"(p));
    return a;
}
__device__ __forceinline__ void ldsm_x4(uint32_t& r0, uint32_t& r1, uint32_t& r2,
                                        uint32_t& r3, uint32_t addr) {
    asm volatile("ldmatrix.sync.aligned.m8n8.x4.shared.b16 {%0,%1,%2,%3}, [%4];"
                 : "=r"(r0), "=r"(r1), "=r"(r2), "=r"(r3) : "r"(addr));
}
__device__ __forceinline__ void mma_f16(float* c, uint32_t a0, uint32_t a1,
                                        uint32_t a2, uint32_t a3,
                                        uint32_t b0, uint32_t b1) {
    asm volatile(
        "mma.sync.aligned.m16n8k16.row.col.f32.f16.f16.f32 "
        "{%0,%1,%2,%3}, {%4,%5,%6,%7}, {%8,%9}, {%0,%1,%2,%3};"
        : "+f"(c[0]), "+f"(c[1]), "+f"(c[2]), "+f"(c[3])
        : "r"(a0), "r"(a1), "r"(a2), "r"(a3), "r"(b0), "r"(b1));
}

// ---------------- scratch (device globals; no allocation allowed) ----------
__device__ __align__(16) float g_X[N_PTS * KPAD];     // K-padded layer input
__device__ __align__(16) float g_AB[N_PTS * NW];
__device__ __align__(16) float g_Wcat_a[KPAD * NW];
__device__ __align__(16) float g_Wcat_b[KPAD * NW];
__device__ int   g_nbr[N_PTS * KNN_K];
__device__ __align__(16) __half g_W2t_a[DTOK * DTOK];
__device__ __align__(16) __half g_W2t_b[DTOK * DTOK];

// ---------------- weight prep (two kernels: profiling alignment) -----------
__global__ void prep_w1(const float* __restrict__ W1a,
                        const float* __restrict__ W1b) {
    int idx = blockIdx.x * blockDim.x + threadIdx.x;
    if (idx >= KPAD * NW) return;
    int r = idx / NW, c = idx % NW;
    float va = 0.f, vb = 0.f;
    if (r < D_IN) {
        if (c < DTOK) {
            va = W1a[r * DTOK + c] - W1a[(D_IN + r) * DTOK + c];
            vb = W1b[r * DTOK + c] - W1b[(D_IN + r) * DTOK + c];
        } else {
            int cc = c - DTOK;
            va = W1a[(D_IN + r) * DTOK + cc];
            vb = W1b[(D_IN + r) * DTOK + cc];
        }
    }
    g_Wcat_a[idx] = va;
    g_Wcat_b[idx] = vb;
}

__global__ void prep_w2(const float* __restrict__ W2a,
                        const float* __restrict__ W2b) {
    int idx = blockIdx.x * blockDim.x + threadIdx.x;
    if (idx >= DTOK * DTOK) return;
    int n = idx / DTOK, d = idx % DTOK;
    g_W2t_a[idx] = __float2half_rn(W2a[d * DTOK + n]);
    g_W2t_b[idx] = __float2half_rn(W2b[d * DTOK + n]);
}

// ---------------- build X1 = [feat | xyz | 0pad] -----------------------------
__global__ void build_x(const float* __restrict__ feat,
                        const float* __restrict__ xyz) {
    int idx = blockIdx.x * blockDim.x + threadIdx.x;
    if (idx >= N_PTS * KPAD) return;
    int i = idx / KPAD, c = idx % KPAD;
    float v = 0.f;
    if (c < DTOK) v = feat[i * DTOK + c];
    else if (c < D_IN) v = xyz[i * 3 + (c - DTOK)];
    g_X[idx] = v;
}

// ---------------- KNN: one warp per query, register top-16 ------------------
#define KNN_WPB   8
#define KNN_TILE  2048
struct DI { float d; int i; };

__global__ __launch_bounds__(256)
void knn_kernel(const float* __restrict__ xyz) {
    __shared__ __align__(16) float4 buf[KNN_TILE];
    int warp = threadIdx.x >> 5, lane = threadIdx.x & 31;
    int q = blockIdx.x * KNN_WPB + warp;

    float xi0 = xyz[q * 3 + 0];
    float xi1 = xyz[q * 3 + 1];
    float xi2 = xyz[q * 3 + 2];
    float sqi = fmaf(xi0, xi0, fmaf(xi1, xi1, xi2 * xi2));

    float d16[KNN_K];
    int   i16[KNN_K];
    #pragma unroll
    for (int s = 0; s < KNN_K; s++) { d16[s] = 1e30f; i16[s] = -1; }

    for (int t0 = 0; t0 < N_PTS; t0 += KNN_TILE) {
        __syncthreads();
        for (int t = threadIdx.x; t < KNN_TILE; t += 256) {
            int j = t0 + t;
            float a = xyz[j * 3 + 0];
            float b = xyz[j * 3 + 1];
            float c = xyz[j * 3 + 2];
            buf[t] = make_float4(a, b, c, fmaf(a, a, fmaf(b, b, c * c)));
        }
        __syncthreads();

        #pragma unroll 4
        for (int jj = lane; jj < KNN_TILE; jj += 32) {
            float4 p = buf[jj];
            float dot = fmaf(xi0, p.x, fmaf(xi1, p.y, xi2 * p.z));
            float dist = (sqi + p.w) - 2.0f * dot;
            int j = t0 + jj;
            if (j == q) dist = 1e30f;
            if (dist < d16[KNN_K - 1]) {
                float dk = dist; int ik = j;
                #pragma unroll
                for (int s = 0; s < KNN_K; s++) {
                    if (dk < d16[s]) {
                        float tf = d16[s]; d16[s] = dk; dk = tf;
                        int   ti = i16[s]; i16[s] = ik; ik = ti;
                    }
                }
            }
        }
    }
    __syncthreads();

    DI* pairs = (DI*)buf;
    DI* wp = pairs + warp * (KNN_K * 32);
    #pragma unroll
    for (int s = 0; s < KNN_K; s++) {
        DI e; e.d = d16[s]; e.i = i16[s];
        wp[s * 32 + lane] = e;
    }
    __syncwarp();

    int ptr = 0;
    #pragma unroll 1
    for (int r = 0; r < KNN_K; r++) {
        DI h = wp[ptr * 32 + lane];
        float bd = h.d; int bi = h.i;
        #pragma unroll
        for (int off = 16; off > 0; off >>= 1) {
            float od = __shfl_xor_sync(0xFFFFFFFFu, bd, off);
            int   oi = __shfl_xor_sync(0xFFFFFFFFu, bi, off);
            if (od < bd || (od == bd && oi < bi)) { bd = od; bi = oi; }
        }
        if (h.d == bd && h.i == bi) ptr++;
        if (lane == 0) g_nbr[q * KNN_K + r] = bi;
    }
}

// ---------------- GEMM1: AB[8192,512] = X[8192,KPAD] @ Wcat[KPAD,512] (+bias)
// 64x128 CTA tile, 4x8 per-thread (f32x2), 2 CTAs/SM.
#define BM 64
#define BN 128
#define BK 16
__global__ __launch_bounds__(256, 2)
void gemm_bias(const float* __restrict__ Xp, const float* __restrict__ Wp,
               const float* __restrict__ bias, float* __restrict__ C,
               int bias_cols) {
    __shared__ __align__(16) float Xs[BK][BM];
    __shared__ __align__(16) float Ws[BK][BN];
    int tid = threadIdx.x;
    int tx = tid % 16, ty = tid / 16;
    int bm = blockIdx.y * BM, bn = blockIdx.x * BN;

    u64 acc[4][4];
    #pragma unroll
    for (int u = 0; u < 4; u++)
        #pragma unroll
        for (int v = 0; v < 4; v++) acc[u][v] = 0ull;

    int xm = tid & 63;            // X row
    int xq = tid >> 6;            // k quad index (0..3)
    int wk = tid >> 5;            // Ws kk row (0..7, +8 second pass)
    int wn = (tid & 31) * 4;      // n quad

    #pragma unroll 1
    for (int k0 = 0; k0 < KPAD; k0 += BK) {
        {
            int kk = xq * 4;
            float4 v = *(const float4*)&Xp[(bm + xm) * KPAD + k0 + kk];
            Xs[kk + 0][xm] = v.x;
            Xs[kk + 1][xm] = v.y;
            Xs[kk + 2][xm] = v.z;
            Xs[kk + 3][xm] = v.w;
        }
        #pragma unroll
        for (int i = 0; i < 2; i++) {
            int kk = wk + i * 8;
            *(float4*)&Ws[kk][wn] = *(const float4*)&Wp[(k0 + kk) * NW + bn + wn];
        }
        __syncthreads();
        #pragma unroll
        for (int kk = 0; kk < BK; kk++) {
            float4 av = *(const float4*)&Xs[kk][ty * 4];
            ulonglong2 b01 = *(const ulonglong2*)&Ws[kk][tx * 8];
            ulonglong2 b23 = *(const ulonglong2*)&Ws[kk][tx * 8 + 4];
            u64 am[4];
            am[0] = pack2(av.x, av.x); am[1] = pack2(av.y, av.y);
            am[2] = pack2(av.z, av.z); am[3] = pack2(av.w, av.w);
            #pragma unroll
            for (int u = 0; u < 4; u++) {
                acc[u][0] = fma2(am[u], b01.x, acc[u][0]);
                acc[u][1] = fma2(am[u], b01.y, acc[u][1]);
                acc[u][2] = fma2(am[u], b23.x, acc[u][2]);
                acc[u][3] = fma2(am[u], b23.y, acc[u][3]);
            }
        }
        __syncthreads();
    }

    bool has_bias = (bn < bias_cols);
    #pragma unroll
    for (int u = 0; u < 4; u++) {
        int m = bm + ty * 4 + u;
        float out8[8];
        #pragma unroll
        for (int v = 0; v < 4; v++) {
            float2 f = unpack2(acc[u][v]);
            out8[v * 2] = f.x; out8[v * 2 + 1] = f.y;
        }
        int n0 = bn + tx * 8;
        if (has_bias) {
            #pragma unroll
            for (int v = 0; v < 8; v++) out8[v] += bias[n0 + v];
        }
        *(float4*)&C[m * NW + n0]     = make_float4(out8[0], out8[1], out8[2], out8[3]);
        *(float4*)&C[m * NW + n0 + 4] = make_float4(out8[4], out8[5], out8[6], out8[7]);
    }
}

// ---------------- edge MMA kernel: warp-level HMMA fp16, 512 threads --------
// Per CTA: 8 points, 128 edge rows. D[128x256] = H[128x256] @ W2t[256x256]^T
// 16 warps: warp w -> point-pair (w>>2): points 2*(w>>2), 2*(w>>2)+1;
//           col quarter (w&3)*64. Each warp: 32 rows x 64 cols, K=256.
#define HS_OFF   0
#define WS_OFF   65536
#define NBR_OFF  196608          // 128 ints
#define B2_OFF   197632          // 256 floats
#define ESMEM_SZ (198656 + 1024)

__global__ __launch_bounds__(512, 1)
void edge_mma(const float* __restrict__ AB, const __half* __restrict__ W2t,
              const float* __restrict__ b2, float* __restrict__ out, int ostride) {
    extern __shared__ __align__(16) char dsm[];
    uint32_t raw = smem_u32(dsm);
    uint32_t base = (raw + 1023u) & ~1023u;
    char* sm = dsm + (base - raw);

    int tid = threadIdx.x;
    int wid = tid >> 5, lane = tid & 31;

    int* snbr = (int*)(sm + NBR_OFF);
    float* b2s = (float*)(sm + B2_OFF);
    if (tid < 128) snbr[tid] = g_nbr[blockIdx.x * 128 + tid];
    if (tid < 256) b2s[tid] = b2[tid];

    // --- load W2t into swizzled SMEM: 8192 x 16B chunks ---
    {
        const uint4* src = (const uint4*)W2t;
        #pragma unroll
        for (int it = 0; it < 16; it++) {
            int i = it * 512 + tid;
            int n = i >> 5, kb = i & 31;
            uint32_t off = (uint32_t)(n * 512 + ((kb * 16) ^ ((n & 7) << 4)));
            *(uint4*)(sm + WS_OFF + off) = src[i];
        }
    }
    __syncthreads();   // snbr ready before H build reads it

    // --- build H tile: h = relu(A_i + B_j), fp16, swizzled (512 thr) ---
    {
        int rowgrp = tid >> 7;                // 0..3 -> 32 rows each
        int c2 = (tid & 127) * 2;             // even column index
        uint32_t cb = (uint32_t)(c2 * 2);     // column byte offset
        float2 a2 = make_float2(0.f, 0.f);
        #pragma unroll 4
        for (int rr = 0; rr < 32; rr++) {
            int r = rowgrp * 32 + rr;
            if ((r & 15) == 0) {
                int pt = blockIdx.x * 8 + (r >> 4);
                a2 = *(const float2*)&AB[pt * NW + c2];
            }
            int j = snbr[r];
            float2 b = *(const float2*)&AB[j * NW + DTOK + c2];
            float h0 = fmaxf(a2.x + b.x, 0.f);
            float h1 = fmaxf(a2.y + b.y, 0.f);
            uint32_t off = (uint32_t)(r * 512) + (cb ^ ((uint32_t)(r & 7) << 4));
            *(__half2*)(sm + HS_OFF + off) = __floats2half2_rn(h0, h1);
        }
    }
    __syncthreads();

    // --- per-warp MMA: 2 points x 64 cols, K=256 ---
    int pp = wid >> 2;                 // point pair 0..3
    int p0 = pp * 2;                   // points p0, p0+1
    int colq = (wid & 3) * 64;         // column quarter
    int ptg0 = blockIdx.x * 8 + p0;

    uint32_t swz = (uint32_t)(lane & 7) << 4;
    uint32_t rowA = (uint32_t)(((lane >> 3) & 1) * 8 + (lane & 7));
    uint32_t baseA0 = base + HS_OFF + (p0 * 16 + rowA) * 512;
    uint32_t baseA1 = baseA0 + 16 * 512;
    uint32_t cbA_add = (uint32_t)(lane >> 4) * 16;
    uint32_t nB_part = (uint32_t)((lane >> 4) * 8 + (lane & 7));
    uint32_t baseB = base + WS_OFF + (colq + nB_part) * 512;
    uint32_t cbB_add = (uint32_t)((lane >> 3) & 1) * 16;

    float acc[2][8][4];
    #pragma unroll
    for (int p = 0; p < 2; p++)
        #pragma unroll
        for (int t = 0; t < 8; t++)
            #pragma unroll
            for (int u = 0; u < 4; u++) acc[p][t][u] = 0.f;

    #pragma unroll 4
    for (int kk = 0; kk < 16; kk++) {
        uint32_t cbA = ((uint32_t)(kk * 32) + cbA_add) ^ swz;
        uint32_t x0, x1, x2, x3, y0, y1, y2, y3;
        ldsm_x4(x0, x1, x2, x3, baseA0 + cbA);
        ldsm_x4(y0, y1, y2, y3, baseA1 + cbA);
        uint32_t cbB = ((uint32_t)(kk * 32) + cbB_add) ^ swz;
        #pragma unroll
        for (int nt = 0; nt < 4; nt++) {
            uint32_t b0, b1, b2r, b3;
            ldsm_x4(b0, b1, b2r, b3, baseB + (uint32_t)(nt * 16 * 512) + cbB);
            mma_f16(acc[0][nt * 2 + 0], x0, x1, x2, x3, b0, b1);
            mma_f16(acc[0][nt * 2 + 1], x0, x1, x2, x3, b2r, b3);
            mma_f16(acc[1][nt * 2 + 0], y0, y1, y2, y3, b0, b1);
            mma_f16(acc[1][nt * 2 + 1], y0, y1, y2, y3, b2r, b3);
        }
    }

    // --- epilogue: max over 16 edge rows per column, per point ---
    int tg = lane & 3;
    #pragma unroll
    for (int p = 0; p < 2; p++) {
        #pragma unroll
        for (int t = 0; t < 8; t++) {
            float m0 = fmaxf(acc[p][t][0], acc[p][t][2]);
            float m1 = fmaxf(acc[p][t][1], acc[p][t][3]);
            #pragma unroll
            for (int off = 4; off <= 16; off <<= 1) {
                m0 = fmaxf(m0, __shfl_xor_sync(0xFFFFFFFFu, m0, off));
                m1 = fmaxf(m1, __shfl_xor_sync(0xFFFFFFFFu, m1, off));
            }
            if (lane < 4) {
                int col = colq + t * 8 + tg * 2;
                *(float2*)&out[(ptg0 + p) * ostride + col] =
                    make_float2(m0 + b2s[col], m1 + b2s[col + 1]);
            }
        }
    }
}

// ---------------- launch ----------------------------------------------------
extern "C" void kernel_launch(void* const* d_in, const int* in_sizes, int n_in,
                              void* d_out, int out_size) {
    const float* xyz  = (const float*)d_in[0];
    const float* feat = (const float*)d_in[1];
    const float* W1a  = (const float*)d_in[2];
    const float* b1a  = (const float*)d_in[3];
    const float* W2a  = (const float*)d_in[4];
    const float* b2a  = (const float*)d_in[5];
    const float* W1b  = (const float*)d_in[6];
    const float* b1b  = (const float*)d_in[7];
    const float* W2b  = (const float*)d_in[8];
    const float* b2b  = (const float*)d_in[9];
    float* out = (float*)d_out;

    float *gX, *gAB, *gWa, *gWb;
    __half *gW2a, *gW2b;
    cudaGetSymbolAddress((void**)&gX,   g_X);
    cudaGetSymbolAddress((void**)&gAB,  g_AB);
    cudaGetSymbolAddress((void**)&gWa,  g_Wcat_a);
    cudaGetSymbolAddress((void**)&gWb,  g_Wcat_b);
    cudaGetSymbolAddress((void**)&gW2a, g_W2t_a);
    cudaGetSymbolAddress((void**)&gW2b, g_W2t_b);

    cudaFuncSetAttribute(edge_mma, cudaFuncAttributeMaxDynamicSharedMemorySize, ESMEM_SZ);

    // 1-2) weight prep (two launches so edge_mma is the 6th launch -> ncu -s 5)
    {
        int n = KPAD * NW;
        prep_w1<<<(n + 255) / 256, 256>>>(W1a, W1b);
        int m = DTOK * DTOK;
        prep_w2<<<(m + 255) / 256, 256>>>(W2a, W2b);
    }
    // 3) KNN
    knn_kernel<<<N_PTS / KNN_WPB, 256>>>(xyz);
    // 4) X1 = [feat | xyz | 0]
    {
        int n = N_PTS * KPAD;
        build_x<<<(n + 255) / 256, 256>>>(feat, xyz);
    }
    dim3 ggrid(NW / BN, N_PTS / BM);

    // layer a
    gemm_bias<<<ggrid, 256>>>(gX, gWa, b1a, gAB, DTOK);          // launch 5
    edge_mma<<<N_PTS / 8, 512, ESMEM_SZ>>>(gAB, gW2a, b2a, gX, KPAD);  // launch 6 (profiled)

    // layer b
    gemm_bias<<<ggrid, 256>>>(gX, gWb, b1b, gAB, DTOK);
    edge_mma<<<N_PTS / 8, 512, ESMEM_SZ>>>(gAB, gW2b, b2b, out, DTOK);
}

// round 17
// speedup vs baseline: 1.0879x; 1.0879x over previous
#include <cuda_runtime.h>
#include <cuda_fp16.h>
#include <cstdint>

#define N_PTS 8192
#define DTOK  256
#define KNN_K 16
#define D_IN  259          // DTOK + 3
#define KPAD  272          // D_IN padded to multiple of 16 (rows 16B-aligned)
#define NW    512          // concatenated output cols of gemm1: [A | B]

typedef unsigned long long u64;

// ---------------- f32x2 packed helpers (sm_100+) ----------------------------
__device__ __forceinline__ u64 pack2(float lo, float hi) {
    u64 r;
    asm("mov.b64 %0, {%1, %2};" : "=l"(r) : "f"(lo), "f"(hi));
    return r;
}
__device__ __forceinline__ u64 fma2(u64 a, u64 b, u64 c) {
    u64 d;
    asm("fma.rn.f32x2 %0, %1, %2, %3;" : "=l"(d) : "l"(a), "l"(b), "l"(c));
    return d;
}
__device__ __forceinline__ float2 unpack2(u64 v) {
    float2 f;
    asm("mov.b64 {%0, %1}, %2;" : "=f"(f.x), "=f"(f.y) : "l"(v));
    return f;
}

// ---------------- warp MMA helpers (family-level PTX) ------------------------
__device__ __forceinline__ uint32_t smem_u32(const void* p) {
    uint32_t a;
    asm("{ .reg .u64 t; cvta.to.shared.u64 t, %1; cvt.u32.u64 %0, t; }" : "=r"(a) : "l"(p));
    return a;
}
__device__ __forceinline__ void ldsm_x4(uint32_t& r0, uint32_t& r1, uint32_t& r2,
                                        uint32_t& r3, uint32_t addr) {
    asm volatile("ldmatrix.sync.aligned.m8n8.x4.shared.b16 {%0,%1,%2,%3}, [%4];"
                 : "=r"(r0), "=r"(r1), "=r"(r2), "=r"(r3) : "r"(addr));
}
__device__ __forceinline__ void mma_f16(float* c, uint32_t a0, uint32_t a1,
                                        uint32_t a2, uint32_t a3,
                                        uint32_t b0, uint32_t b1) {
    asm volatile(
        "mma.sync.aligned.m16n8k16.row.col.f32.f16.f16.f32 "
        "{%0,%1,%2,%3}, {%4,%5,%6,%7}, {%8,%9}, {%0,%1,%2,%3};"
        : "+f"(c[0]), "+f"(c[1]), "+f"(c[2]), "+f"(c[3])
        : "r"(a0), "r"(a1), "r"(a2), "r"(a3), "r"(b0), "r"(b1));
}

// ---------------- scratch (device globals; no allocation allowed) ----------
__device__ __align__(16) float g_X[N_PTS * KPAD];     // K-padded layer input
__device__ __align__(16) float g_AB[N_PTS * NW];
__device__ __align__(16) float g_Wcat_a[KPAD * NW];
__device__ __align__(16) float g_Wcat_b[KPAD * NW];
__device__ int   g_nbr[N_PTS * KNN_K];
__device__ __align__(16) __half g_W2t_a[DTOK * DTOK];
__device__ __align__(16) __half g_W2t_b[DTOK * DTOK];

// ---------------- fused prep: Wcat + W2t + X1 in one launch -----------------
__global__ void prep_all(const float* __restrict__ W1a,
                         const float* __restrict__ W1b,
                         const float* __restrict__ W2a,
                         const float* __restrict__ W2b,
                         const float* __restrict__ feat,
                         const float* __restrict__ xyz) {
    int idx = blockIdx.x * blockDim.x + threadIdx.x;
    if (idx < KPAD * NW) {
        int r = idx / NW, c = idx % NW;
        float va = 0.f, vb = 0.f;
        if (r < D_IN) {
            if (c < DTOK) {
                va = W1a[r * DTOK + c] - W1a[(D_IN + r) * DTOK + c];
                vb = W1b[r * DTOK + c] - W1b[(D_IN + r) * DTOK + c];
            } else {
                int cc = c - DTOK;
                va = W1a[(D_IN + r) * DTOK + cc];
                vb = W1b[(D_IN + r) * DTOK + cc];
            }
        }
        g_Wcat_a[idx] = va;
        g_Wcat_b[idx] = vb;
    }
    if (idx < DTOK * DTOK) {
        int n = idx / DTOK, d = idx % DTOK;
        g_W2t_a[idx] = __float2half_rn(W2a[d * DTOK + n]);
        g_W2t_b[idx] = __float2half_rn(W2b[d * DTOK + n]);
    }
    if (idx < N_PTS * KPAD) {
        int i = idx / KPAD, c = idx % KPAD;
        float v = 0.f;
        if (c < DTOK) v = feat[i * DTOK + c];
        else if (c < D_IN) v = xyz[i * 3 + (c - DTOK)];
        g_X[idx] = v;
    }
}

// ---------------- KNN: one warp per query, register top-16 ------------------
#define KNN_WPB   8
#define KNN_TILE  2048
struct DI { float d; int i; };

__global__ __launch_bounds__(256)
void knn_kernel(const float* __restrict__ xyz) {
    __shared__ __align__(16) float4 buf[KNN_TILE];
    int warp = threadIdx.x >> 5, lane = threadIdx.x & 31;
    int q = blockIdx.x * KNN_WPB + warp;

    float xi0 = xyz[q * 3 + 0];
    float xi1 = xyz[q * 3 + 1];
    float xi2 = xyz[q * 3 + 2];
    float sqi = fmaf(xi0, xi0, fmaf(xi1, xi1, xi2 * xi2));

    float d16[KNN_K];
    int   i16[KNN_K];
    #pragma unroll
    for (int s = 0; s < KNN_K; s++) { d16[s] = 1e30f; i16[s] = -1; }

    for (int t0 = 0; t0 < N_PTS; t0 += KNN_TILE) {
        __syncthreads();
        for (int t = threadIdx.x; t < KNN_TILE; t += 256) {
            int j = t0 + t;
            float a = xyz[j * 3 + 0];
            float b = xyz[j * 3 + 1];
            float c = xyz[j * 3 + 2];
            buf[t] = make_float4(a, b, c, fmaf(a, a, fmaf(b, b, c * c)));
        }
        __syncthreads();

        #pragma unroll 4
        for (int jj = lane; jj < KNN_TILE; jj += 32) {
            float4 p = buf[jj];
            float dot = fmaf(xi0, p.x, fmaf(xi1, p.y, xi2 * p.z));
            float dist = (sqi + p.w) - 2.0f * dot;
            int j = t0 + jj;
            if (j == q) dist = 1e30f;
            if (dist < d16[KNN_K - 1]) {
                float dk = dist; int ik = j;
                #pragma unroll
                for (int s = 0; s < KNN_K; s++) {
                    if (dk < d16[s]) {
                        float tf = d16[s]; d16[s] = dk; dk = tf;
                        int   ti = i16[s]; i16[s] = ik; ik = ti;
                    }
                }
            }
        }
    }
    __syncthreads();

    DI* pairs = (DI*)buf;
    DI* wp = pairs + warp * (KNN_K * 32);
    #pragma unroll
    for (int s = 0; s < KNN_K; s++) {
        DI e; e.d = d16[s]; e.i = i16[s];
        wp[s * 32 + lane] = e;
    }
    __syncwarp();

    int ptr = 0;
    #pragma unroll 1
    for (int r = 0; r < KNN_K; r++) {
        DI h = wp[ptr * 32 + lane];
        float bd = h.d; int bi = h.i;
        #pragma unroll
        for (int off = 16; off > 0; off >>= 1) {
            float od = __shfl_xor_sync(0xFFFFFFFFu, bd, off);
            int   oi = __shfl_xor_sync(0xFFFFFFFFu, bi, off);
            if (od < bd || (od == bd && oi < bi)) { bd = od; bi = oi; }
        }
        if (h.d == bd && h.i == bi) ptr++;
        if (lane == 0) g_nbr[q * KNN_K + r] = bi;
    }
}

// ---------------- GEMM1: AB[8192,512] = X[8192,KPAD] @ Wcat[KPAD,512] (+bias)
// 128x128 CTA tile, 8x8 per-thread (f32x2), K padded -> no guards. (round-13)
#define BM 128
#define BN 128
#define BK 16
__global__ __launch_bounds__(256)
void gemm_bias(const float* __restrict__ Xp, const float* __restrict__ Wp,
               const float* __restrict__ bias, float* __restrict__ C,
               int bias_cols) {
    __shared__ __align__(16) float Xs[BK][BM];
    __shared__ __align__(16) float Ws[BK][BN];
    int tid = threadIdx.x;
    int tx = tid % 16, ty = tid / 16;
    int bm = blockIdx.y * BM, bn = blockIdx.x * BN;

    u64 acc[8][4];
    #pragma unroll
    for (int u = 0; u < 8; u++)
        #pragma unroll
        for (int v = 0; v < 4; v++) acc[u][v] = 0ull;

    int xm = tid & 127;           // row this thread loads for Xs
    int xq = tid >> 7;            // kk block 0/1
    int wk = tid >> 5;            // kk row for Ws (0..7, +8 on second pass)
    int wn = (tid & 31) * 4;      // n quad

    #pragma unroll 1
    for (int k0 = 0; k0 < KPAD; k0 += BK) {
        #pragma unroll
        for (int i = 0; i < 2; i++) {
            int kk = xq * 8 + i * 4;
            float4 v = *(const float4*)&Xp[(bm + xm) * KPAD + k0 + kk];
            Xs[kk + 0][xm] = v.x;
            Xs[kk + 1][xm] = v.y;
            Xs[kk + 2][xm] = v.z;
            Xs[kk + 3][xm] = v.w;
        }
        #pragma unroll
        for (int i = 0; i < 2; i++) {
            int kk = wk + i * 8;
            *(float4*)&Ws[kk][wn] = *(const float4*)&Wp[(k0 + kk) * NW + bn + wn];
        }
        __syncthreads();
        #pragma unroll
        for (int kk = 0; kk < BK; kk++) {
            float4 aLo = *(const float4*)&Xs[kk][ty * 8];
            float4 aHi = *(const float4*)&Xs[kk][ty * 8 + 4];
            ulonglong2 b01 = *(const ulonglong2*)&Ws[kk][tx * 8];
            ulonglong2 b23 = *(const ulonglong2*)&Ws[kk][tx * 8 + 4];
            u64 am[8];
            am[0] = pack2(aLo.x, aLo.x); am[1] = pack2(aLo.y, aLo.y);
            am[2] = pack2(aLo.z, aLo.z); am[3] = pack2(aLo.w, aLo.w);
            am[4] = pack2(aHi.x, aHi.x); am[5] = pack2(aHi.y, aHi.y);
            am[6] = pack2(aHi.z, aHi.z); am[7] = pack2(aHi.w, aHi.w);
            #pragma unroll
            for (int u = 0; u < 8; u++) {
                acc[u][0] = fma2(am[u], b01.x, acc[u][0]);
                acc[u][1] = fma2(am[u], b01.y, acc[u][1]);
                acc[u][2] = fma2(am[u], b23.x, acc[u][2]);
                acc[u][3] = fma2(am[u], b23.y, acc[u][3]);
            }
        }
        __syncthreads();
    }

    bool has_bias = (bn < bias_cols);
    #pragma unroll
    for (int u = 0; u < 8; u++) {
        int m = bm + ty * 8 + u;
        float out8[8];
        #pragma unroll
        for (int v = 0; v < 4; v++) {
            float2 f = unpack2(acc[u][v]);
            out8[v * 2] = f.x; out8[v * 2 + 1] = f.y;
        }
        int n0 = bn + tx * 8;
        if (has_bias) {
            #pragma unroll
            for (int v = 0; v < 8; v++) out8[v] += bias[n0 + v];
        }
        *(float4*)&C[m * NW + n0]     = make_float4(out8[0], out8[1], out8[2], out8[3]);
        *(float4*)&C[m * NW + n0 + 4] = make_float4(out8[4], out8[5], out8[6], out8[7]);
    }
}

// ---------------- edge MMA kernel (round-13): 512 thr, warp = pt x N-half ---
#define HS_OFF   0
#define WS_OFF   65536
#define NBR_OFF  196608          // 128 ints
#define B2_OFF   197632          // 256 floats
#define ESMEM_SZ (198656 + 1024)

__global__ __launch_bounds__(512, 1)
void edge_mma(const float* __restrict__ AB, const __half* __restrict__ W2t,
              const float* __restrict__ b2, float* __restrict__ out, int ostride) {
    extern __shared__ __align__(16) char dsm[];
    uint32_t raw = smem_u32(dsm);
    uint32_t base = (raw + 1023u) & ~1023u;
    char* sm = dsm + (base - raw);

    int tid = threadIdx.x;
    int wid = tid >> 5, lane = tid & 31;

    int* snbr = (int*)(sm + NBR_OFF);
    float* b2s = (float*)(sm + B2_OFF);
    if (tid < 128) snbr[tid] = g_nbr[blockIdx.x * 128 + tid];
    if (tid < 256) b2s[tid] = b2[tid];

    // --- load W2t into swizzled SMEM: 8192 x 16B chunks ---
    {
        const uint4* src = (const uint4*)W2t;
        #pragma unroll
        for (int it = 0; it < 16; it++) {
            int i = it * 512 + tid;
            int n = i >> 5, kb = i & 31;
            uint32_t off = (uint32_t)(n * 512 + ((kb * 16) ^ ((n & 7) << 4)));
            *(uint4*)(sm + WS_OFF + off) = src[i];
        }
    }
    __syncthreads();   // snbr ready before H build reads it

    // --- build H tile: h = relu(A_i + B_j), fp16, swizzled (512 thr) ---
    {
        int rowgrp = tid >> 7;                // 0..3 -> 32 rows each
        int c2 = (tid & 127) * 2;             // even column index
        uint32_t cb = (uint32_t)(c2 * 2);     // column byte offset
        float2 a2 = make_float2(0.f, 0.f);
        #pragma unroll 4
        for (int rr = 0; rr < 32; rr++) {
            int r = rowgrp * 32 + rr;
            if ((r & 15) == 0) {
                int pt = blockIdx.x * 8 + (r >> 4);
                a2 = *(const float2*)&AB[pt * NW + c2];
            }
            int j = snbr[r];
            float2 b = *(const float2*)&AB[j * NW + DTOK + c2];
            float h0 = fmaxf(a2.x + b.x, 0.f);
            float h1 = fmaxf(a2.y + b.y, 0.f);
            uint32_t off = (uint32_t)(r * 512) + (cb ^ ((uint32_t)(r & 7) << 4));
            *(__half2*)(sm + HS_OFF + off) = __floats2half2_rn(h0, h1);
        }
    }
    __syncthreads();

    // --- per-warp MMA: point pt = wid>>1, N-half (wid&1), 16 rows x 128 cols
    int pt = wid >> 1;
    int nhalf = wid & 1;
    int ptg = blockIdx.x * 8 + pt;
    uint32_t swz = (uint32_t)(lane & 7) << 4;
    uint32_t rowA = (uint32_t)(pt * 16 + ((lane >> 3) & 1) * 8 + (lane & 7));
    uint32_t baseA = base + HS_OFF + rowA * 512;
    uint32_t cbA_add = (uint32_t)(lane >> 4) * 16;
    uint32_t nB_part = (uint32_t)((lane >> 4) * 8 + (lane & 7));
    uint32_t baseB = base + WS_OFF + nB_part * 512;
    uint32_t cbB_add = (uint32_t)((lane >> 3) & 1) * 16;

    int tg = lane & 3;            // thread-in-group: column pair selector
    #pragma unroll 1
    for (int chunk = 0; chunk < 2; chunk++) {
        int n0c = nhalf * 128 + chunk * 64;
        float acc[8][4];
        #pragma unroll
        for (int t = 0; t < 8; t++)
            #pragma unroll
            for (int u = 0; u < 4; u++) acc[t][u] = 0.f;

        #pragma unroll 4
        for (int kk = 0; kk < 16; kk++) {
            uint32_t a0, a1, a2r, a3;
            uint32_t cbA = (uint32_t)(kk * 32) + cbA_add;
            ldsm_x4(a0, a1, a2r, a3, baseA + (cbA ^ swz));
            uint32_t cbB = (uint32_t)(kk * 32) + cbB_add;
            #pragma unroll
            for (int ntp = 0; ntp < 4; ntp++) {
                uint32_t b0, b1, b2r, b3;
                uint32_t nOff = (uint32_t)((n0c + ntp * 16) * 512);
                ldsm_x4(b0, b1, b2r, b3, baseB + nOff + (cbB ^ swz));
                mma_f16(acc[ntp * 2 + 0], a0, a1, a2r, a3, b0, b1);
                mma_f16(acc[ntp * 2 + 1], a0, a1, a2r, a3, b2r, b3);
            }
        }

        // epilogue: max over 16 edge rows per column
        #pragma unroll
        for (int t = 0; t < 8; t++) {
            float m0 = fmaxf(acc[t][0], acc[t][2]);
            float m1 = fmaxf(acc[t][1], acc[t][3]);
            #pragma unroll
            for (int off = 4; off <= 16; off <<= 1) {
                m0 = fmaxf(m0, __shfl_xor_sync(0xFFFFFFFFu, m0, off));
                m1 = fmaxf(m1, __shfl_xor_sync(0xFFFFFFFFu, m1, off));
            }
            if (lane < 4) {
                int col = n0c + t * 8 + tg * 2;
                *(float2*)&out[ptg * ostride + col] =
                    make_float2(m0 + b2s[col], m1 + b2s[col + 1]);
            }
        }
    }
}

// ---------------- launch ----------------------------------------------------
extern "C" void kernel_launch(void* const* d_in, const int* in_sizes, int n_in,
                              void* d_out, int out_size) {
    const float* xyz  = (const float*)d_in[0];
    const float* feat = (const float*)d_in[1];
    const float* W1a  = (const float*)d_in[2];
    const float* b1a  = (const float*)d_in[3];
    const float* W2a  = (const float*)d_in[4];
    const float* b2a  = (const float*)d_in[5];
    const float* W1b  = (const float*)d_in[6];
    const float* b1b  = (const float*)d_in[7];
    const float* W2b  = (const float*)d_in[8];
    const float* b2b  = (const float*)d_in[9];
    float* out = (float*)d_out;

    float *gX, *gAB, *gWa, *gWb;
    __half *gW2a, *gW2b;
    cudaGetSymbolAddress((void**)&gX,   g_X);
    cudaGetSymbolAddress((void**)&gAB,  g_AB);
    cudaGetSymbolAddress((void**)&gWa,  g_Wcat_a);
    cudaGetSymbolAddress((void**)&gWb,  g_Wcat_b);
    cudaGetSymbolAddress((void**)&gW2a, g_W2t_a);
    cudaGetSymbolAddress((void**)&gW2b, g_W2t_b);

    cudaFuncSetAttribute(edge_mma, cudaFuncAttributeMaxDynamicSharedMemorySize, ESMEM_SZ);

    // 1) fused prep (Wcat + W2t + X1) — keeps total launches at 6 so the
    //    ncu -s 5 -c 1 window lands on edge_mma (launch #6, layer b)
    {
        int n = N_PTS * KPAD;   // largest of the three fused index spaces
        prep_all<<<(n + 255) / 256, 256>>>(W1a, W1b, W2a, W2b, feat, xyz);
    }
    // 2) KNN
    knn_kernel<<<N_PTS / KNN_WPB, 256>>>(xyz);

    dim3 ggrid(NW / BN, N_PTS / BM);

    // layer a
    gemm_bias<<<ggrid, 256>>>(gX, gWa, b1a, gAB, DTOK);                 // 3
    edge_mma<<<N_PTS / 8, 512, ESMEM_SZ>>>(gAB, gW2a, b2a, gX, KPAD);   // 4

    // layer b
    gemm_bias<<<ggrid, 256>>>(gX, gWb, b1b, gAB, DTOK);                 // 5
    edge_mma<<<N_PTS / 8, 512, ESMEM_SZ>>>(gAB, gW2b, b2b, out, DTOK);  // 6 (profiled)
}